// round 12
// baseline (speedup 1.0000x reference)
#include <cuda_runtime.h>
#include <cstdint>

// NATTEN 7x7, B=2, heads=8, d=32, 56x56, fp32.
// x: (B,768,56,56) qkv-packed; rpb: (8,13,13); out: (B,256,56,56).
// 256 threads/CTA (64x4, 8 warps; lanes tx>=56 are loader-only), each active
// thread owns 2 vertically-adjacent queries; 8-row stripe per CTA.
// Fused single pass per tap (QK -> ex2 -> AV), log2-domain, no max-shift.

#define HH 56
#define WW 56
#define PLANE 3136
#define ROWS 8
#define SROWS 14
#define BW 64                     // block width (56 active + 8 loader-only)
#define NT 256
#define CS 36                     // padded d-stride per (row,col) slot
#define TSLOTS (SROWS * WW)       // 784
#define TELEMS (TSLOTS * CS)      // 28224 floats per tensor
#define LOG2E 1.4426950408889634f

__device__ __forceinline__ uint64_t pack2(float lo, float hi) {
    uint64_t r; asm("mov.b64 %0, {%1,%2};" : "=l"(r) : "f"(lo), "f"(hi)); return r;
}
__device__ __forceinline__ float2 unpack2(uint64_t v) {
    float2 f; asm("mov.b64 {%0,%1}, %2;" : "=f"(f.x), "=f"(f.y) : "l"(v)); return f;
}
__device__ __forceinline__ uint64_t ffma2(uint64_t a, uint64_t b, uint64_t c) {
    uint64_t d; asm("fma.rn.f32x2 %0, %1, %2, %3;" : "=l"(d) : "l"(a), "l"(b), "l"(c)); return d;
}
__device__ __forceinline__ uint64_t fadd2(uint64_t a, uint64_t b) {
    uint64_t d; asm("add.rn.f32x2 %0, %1, %2;" : "=l"(d) : "l"(a), "l"(b)); return d;
}
__device__ __forceinline__ void lds16(uint32_t a, uint64_t& x, uint64_t& y) {
    asm volatile("ld.shared.v2.b64 {%0,%1}, [%2];" : "=l"(x), "=l"(y) : "r"(a));
}
__device__ __forceinline__ float ex2(float x) {
    float y; asm("ex2.approx.f32 %0, %1;" : "=f"(y) : "f"(x)); return y;
}

__global__ __launch_bounds__(NT, 1)
void natten7x7_kernel(const float* __restrict__ x,
                      const float* __restrict__ rpb,
                      float* __restrict__ out)
{
    extern __shared__ float smem[];
    float* ks = smem;                 // [784][36]
    float* vs = smem + TELEMS;
    float* rs = smem + 2 * TELEMS;    // [192] rpb*log2e (pad covers guarded idx <= 181)

    const int bh = blockIdx.y, b = bh >> 3, head = bh & 7;
    const int i0 = blockIdx.x * ROWS;
    const int r0 = min(max(i0 - 3, 0), HH - SROWS);

    const int tx = threadIdx.x;           // 0..63 (0..55 compute, rest loader-only)
    const int ty = threadIdx.y;           // 0..3
    const int tid = ty * BW + tx;         // 0..255

    const float* xb = x + (size_t)b * (768 * PLANE);
    const float* kg = xb + (size_t)(256 + head * 32) * PLANE + r0 * WW;
    const float* vg = xb + (size_t)(512 + head * 32) * PLANE + r0 * WW;

    if (tid < 169) rs[tid] = rpb[head * 169 + tid] * LOG2E;

    // ---- transpose-load K/V, division-free: slot index linear on both sides ----
    #pragma unroll
    for (int s = 0; s < 4; s++) {
        const int slot = tid + s * NT;
        if (s < 3 || slot < TSLOTS) {
            float* kd = ks + slot * CS;
            float* vd = vs + slot * CS;
            #pragma unroll
            for (int dblk = 0; dblk < 8; dblk++) {
                const float* pk = kg + dblk * 4 * PLANE + slot;
                const float* pv = vg + dblk * 4 * PLANE + slot;
                *(float4*)(kd + dblk * 4) = make_float4(pk[0], pk[PLANE], pk[2 * PLANE], pk[3 * PLANE]);
                *(float4*)(vd + dblk * 4) = make_float4(pv[0], pv[PLANE], pv[2 * PLANE], pv[3 * PLANE]);
            }
        }
    }

    const bool active = (tx < WW);
    const int j = active ? tx : (WW - 1);     // clamped for safe (unused) addressing

    // ---- load + pack q for both rows (scale includes log2e) ----
    const int iA = i0 + 2 * ty, iB = iA + 1;
    const float scale = 0.17677669529663687f * LOG2E;
    uint64_t qA[16], qB[16];
    if (active) {
        const float* qa = xb + (size_t)(head * 32) * PLANE + iA * WW + j;
        const float* qb = qa + WW;
        #pragma unroll
        for (int t = 0; t < 16; t++) {
            qA[t] = pack2(qa[(2 * t) * PLANE] * scale, qa[(2 * t + 1) * PLANE] * scale);
            qB[t] = pack2(qb[(2 * t) * PLANE] * scale, qb[(2 * t + 1) * PLANE] * scale);
        }
    }
    __syncthreads();

    if (!active) return;   // after the only barrier; loader lanes exit

    // ---- window geometry (union of two 7-row windows = 8 rows, off in {0,1}) ----
    const int niA = min(max(iA - 3, 0), HH - 7);
    const int niB = min(max(iB - 3, 0), HH - 7);
    const int off = niB - niA;
    const int piA = 6 - (iA - niA);
    const int piB = 6 - (iB - niB);
    const int nj  = min(max(j - 3, 0), WW - 7);
    const int pj  = 6 - (j - nj);
    const int rbase = niA - r0;   // 0..7 (7 only in edge stripes, where off==0)

    const uint32_t sbase = (uint32_t)__cvta_generic_to_shared(ks) + (uint32_t)(nj * CS * 4);

    float sA = 0.f, sB = 0.f;
    uint64_t oA[16], oB[16];
    #pragma unroll
    for (int t = 0; t < 16; t++) { oA[t] = 0ull; oB[t] = 0ull; }

    // ---- fused pass: per tap, QK -> ex2 -> AV; clamped rows fully masked ----
    #pragma unroll
    for (int rr = 0; rr < 8; rr++) {
        const int  sr = min(rbase + rr, SROWS - 1);
        const bool vB = off ? (rr >= 1) : (rr <= 6);
        const uint32_t rk = sbase + (uint32_t)(sr * (WW * CS * 4));
        const uint32_t rv = rk + (uint32_t)(TELEMS * 4);

        #pragma unroll
        for (int kj = 0; kj < 7; kj++) {
            const uint32_t ak = rk + (uint32_t)(kj * (CS * 4));
            const uint32_t av = rv + (uint32_t)(kj * (CS * 4));
            uint64_t kt[16], vt[16];
            #pragma unroll
            for (int u = 0; u < 8; u++) lds16(ak + 16 * u, kt[2 * u], kt[2 * u + 1]);
            #pragma unroll
            for (int u = 0; u < 8; u++) lds16(av + 16 * u, vt[2 * u], vt[2 * u + 1]);

            if (rr < 7) {
                uint64_t a0 = ffma2(qA[0], kt[0], 0ull);
                uint64_t a1 = ffma2(qA[1], kt[1], 0ull);
                #pragma unroll
                for (int t = 2; t < 16; t += 2) {
                    a0 = ffma2(qA[t],     kt[t],     a0);
                    a1 = ffma2(qA[t + 1], kt[t + 1], a1);
                }
                float2 f = unpack2(fadd2(a0, a1));
                const float w = ex2(f.x + f.y + rs[(piA + rr) * 13 + pj + kj]);
                sA += w;
                const uint64_t w2 = pack2(w, w);
                #pragma unroll
                for (int t = 0; t < 16; t++) oA[t] = ffma2(w2, vt[t], oA[t]);
            }
            {
                uint64_t b0 = ffma2(qB[0], kt[0], 0ull);
                uint64_t b1 = ffma2(qB[1], kt[1], 0ull);
                #pragma unroll
                for (int t = 2; t < 16; t += 2) {
                    b0 = ffma2(qB[t],     kt[t],     b0);
                    b1 = ffma2(qB[t + 1], kt[t + 1], b1);
                }
                float2 f = unpack2(fadd2(b0, b1));
                const float bias = vB ? rs[(piB + rr - off) * 13 + pj + kj] : -1e30f;
                const float w = ex2(f.x + f.y + bias);
                sB += w;
                const uint64_t w2 = pack2(w, w);
                #pragma unroll
                for (int t = 0; t < 16; t++) oB[t] = ffma2(w2, vt[t], oB[t]);
            }
        }
    }
    const float invA = 1.0f / sA, invB = 1.0f / sB;

    // ---- write out (B,256,56,56) ----
    float* oga = out + (size_t)b * (256 * PLANE) + (size_t)(head * 32) * PLANE + iA * WW + j;
    float* ogb = oga + WW;
    #pragma unroll
    for (int t = 0; t < 16; t++) {
        float2 fa = unpack2(oA[t]);
        float2 fb = unpack2(oB[t]);
        oga[(2 * t) * PLANE]     = fa.x * invA;
        oga[(2 * t + 1) * PLANE] = fa.y * invA;
        ogb[(2 * t) * PLANE]     = fb.x * invB;
        ogb[(2 * t + 1) * PLANE] = fb.y * invB;
    }
}

extern "C" void kernel_launch(void* const* d_in, const int* in_sizes, int n_in,
                              void* d_out, int out_size)
{
    const float* x   = (const float*)d_in[0];
    const float* rpb = (const float*)d_in[1];
    float* out = (float*)d_out;

    const int smem_bytes = (2 * TELEMS + 192) * sizeof(float);  // 226,560 B
    cudaFuncSetAttribute(natten7x7_kernel,
                         cudaFuncAttributeMaxDynamicSharedMemorySize, smem_bytes);

    dim3 grid(HH / ROWS, 2 * 8);   // 7 x 16 = 112 CTAs -> single wave
    dim3 block(BW, 4);             // 256 threads (8 warps), 224 compute lanes
    natten7x7_kernel<<<grid, block, smem_bytes>>>(x, rpb, out);
}

// round 13
// speedup vs baseline: 1.0117x; 1.0117x over previous
#include <cuda_runtime.h>
#include <cuda_fp16.h>
#include <cstdint>

// NATTEN 7x7, B=2, heads=8, d=32, 56x56, fp32.
// x: (B,768,56,56) qkv-packed; rpb: (8,13,13); out: (B,256,56,56).
// 224 threads/CTA, 2 vertically-adjacent queries/thread, 8-row stripe.
// Two-pass, log2-domain weights stored as fp16x2 (frees ~52 regs), d-halved
// kt/vt chunks (frees 16 regs/tap) -> register slack for cross-tap pipelining.

#define HH 56
#define WW 56
#define PLANE 3136
#define ROWS 8
#define SROWS 14
#define NT 224
#define CS 36
#define TSLOTS (SROWS * WW)       // 784
#define TELEMS (TSLOTS * CS)      // 28224 floats per tensor
#define LOG2E 1.4426950408889634f

__device__ __forceinline__ uint64_t pack2(float lo, float hi) {
    uint64_t r; asm("mov.b64 %0, {%1,%2};" : "=l"(r) : "f"(lo), "f"(hi)); return r;
}
__device__ __forceinline__ float2 unpack2(uint64_t v) {
    float2 f; asm("mov.b64 {%0,%1}, %2;" : "=f"(f.x), "=f"(f.y) : "l"(v)); return f;
}
__device__ __forceinline__ uint64_t ffma2(uint64_t a, uint64_t b, uint64_t c) {
    uint64_t d; asm("fma.rn.f32x2 %0, %1, %2, %3;" : "=l"(d) : "l"(a), "l"(b), "l"(c)); return d;
}
__device__ __forceinline__ uint64_t fadd2(uint64_t a, uint64_t b) {
    uint64_t d; asm("add.rn.f32x2 %0, %1, %2;" : "=l"(d) : "l"(a), "l"(b)); return d;
}
__device__ __forceinline__ void lds16(uint32_t a, uint64_t& x, uint64_t& y) {
    asm volatile("ld.shared.v2.b64 {%0,%1}, [%2];" : "=l"(x), "=l"(y) : "r"(a));
}
__device__ __forceinline__ float ex2(float x) {
    float y; asm("ex2.approx.f32 %0, %1;" : "=f"(y) : "f"(x)); return y;
}

__global__ __launch_bounds__(NT, 1)
void natten7x7_kernel(const float* __restrict__ x,
                      const float* __restrict__ rpb,
                      float* __restrict__ out)
{
    extern __shared__ float smem[];
    float* ks = smem;                 // [784][36]
    float* vs = smem + TELEMS;
    float* rs = smem + 2 * TELEMS;    // [192] rpb*log2e (pad covers guarded idx <= 181)

    const int bh = blockIdx.y, b = bh >> 3, head = bh & 7;
    const int i0 = blockIdx.x * ROWS;
    const int r0 = min(max(i0 - 3, 0), HH - SROWS);

    const int tx = threadIdx.x, ty = threadIdx.y;
    const int tid = ty * WW + tx;

    const float* xb = x + (size_t)b * (768 * PLANE);
    const float* kg = xb + (size_t)(256 + head * 32) * PLANE + r0 * WW;
    const float* vg = xb + (size_t)(512 + head * 32) * PLANE + r0 * WW;

    if (tid < 169) rs[tid] = rpb[head * 169 + tid] * LOG2E;

    // ---- transpose-load K/V, division-free slot loader ----
    #pragma unroll
    for (int s = 0; s < 4; s++) {
        const int slot = tid + s * NT;
        if (s < 3 || slot < TSLOTS) {
            float* kd = ks + slot * CS;
            float* vd = vs + slot * CS;
            #pragma unroll
            for (int dblk = 0; dblk < 8; dblk++) {
                const float* pk = kg + dblk * 4 * PLANE + slot;
                const float* pv = vg + dblk * 4 * PLANE + slot;
                *(float4*)(kd + dblk * 4) = make_float4(pk[0], pk[PLANE], pk[2 * PLANE], pk[3 * PLANE]);
                *(float4*)(vd + dblk * 4) = make_float4(pv[0], pv[PLANE], pv[2 * PLANE], pv[3 * PLANE]);
            }
        }
    }

    // ---- load + pack q for both rows (scale includes log2e) ----
    const int iA = i0 + 2 * ty, iB = iA + 1, j = tx;
    const float scale = 0.17677669529663687f * LOG2E;
    uint64_t qA[16], qB[16];
    {
        const float* qa = xb + (size_t)(head * 32) * PLANE + iA * WW + j;
        const float* qb = qa + WW;
        #pragma unroll
        for (int t = 0; t < 16; t++) {
            qA[t] = pack2(qa[(2 * t) * PLANE] * scale, qa[(2 * t + 1) * PLANE] * scale);
            qB[t] = pack2(qb[(2 * t) * PLANE] * scale, qb[(2 * t + 1) * PLANE] * scale);
        }
    }
    __syncthreads();

    // ---- window geometry ----
    const int niA = min(max(iA - 3, 0), HH - 7);
    const int niB = min(max(iB - 3, 0), HH - 7);
    const int off = niB - niA;
    const int piA = 6 - (iA - niA);
    const int piB = 6 - (iB - niB);
    const int nj  = min(max(j - 3, 0), WW - 7);
    const int pj  = 6 - (j - nj);
    const int rbase = niA - r0;   // 0..7 (7 only in edge stripes, where off==0)

    const uint32_t sbase = (uint32_t)__cvta_generic_to_shared(ks) + (uint32_t)(nj * CS * 4);

    int srow[8];
    #pragma unroll
    for (int rr = 0; rr < 8; rr++) srow[rr] = min(rbase + rr, SROWS - 1);

    // ---- pass 1: weights = ex2(dot + bias'), stored fp16x2; masked -> 0 ----
    __half2 pAh[25], pBh[28];
    float pendA = 0.f, pendB = 0.f;
    float sA = 0.f, sB = 0.f;
    #pragma unroll
    for (int rr = 0; rr < 8; rr++) {
        const bool vB = off ? (rr >= 1) : (rr <= 6);
        #pragma unroll
        for (int kj = 0; kj < 7; kj++) {
            const uint32_t a = sbase + (uint32_t)((srow[rr] * WW + kj) * CS * 4);
            uint64_t a0 = 0ull, a1 = 0ull, b0 = 0ull, b1 = 0ull;
            #pragma unroll
            for (int h = 0; h < 2; h++) {     // d-halved: 16-reg kt window
                uint64_t kt[8];
                #pragma unroll
                for (int u = 0; u < 4; u++) lds16(a + 64 * h + 16 * u, kt[2 * u], kt[2 * u + 1]);
                #pragma unroll
                for (int t = 0; t < 8; t += 2) {
                    if (rr < 7) {
                        a0 = ffma2(qA[8 * h + t],     kt[t],     a0);
                        a1 = ffma2(qA[8 * h + t + 1], kt[t + 1], a1);
                    }
                    b0 = ffma2(qB[8 * h + t],     kt[t],     b0);
                    b1 = ffma2(qB[8 * h + t + 1], kt[t + 1], b1);
                }
            }
            if (rr < 7) {
                float2 f = unpack2(fadd2(a0, a1));
                const float w = ex2(f.x + f.y + rs[(piA + rr) * 13 + pj + kj]);
                sA += w;
                const int tap = rr * 7 + kj;
                if (tap & 1) pAh[tap >> 1] = __floats2half2_rn(pendA, w);
                else         pendA = w;
            }
            {
                float2 f = unpack2(fadd2(b0, b1));
                const float bias = vB ? rs[(piB + rr - off) * 13 + pj + kj] : -1e30f;
                const float w = ex2(f.x + f.y + bias);
                sB += w;
                const int tap = rr * 7 + kj;
                if (tap & 1) pBh[tap >> 1] = __floats2half2_rn(pendB, w);
                else         pendB = w;
            }
        }
    }
    pAh[24] = __floats2half2_rn(pendA, 0.f);   // A has 49 taps (odd count)
    const float invA = 1.0f / sA, invB = 1.0f / sB;

    // ---- pass 2: AV (shared V reads feed both queries) ----
    const uint32_t vbase = sbase + (uint32_t)(TELEMS * 4);
    uint64_t oA[16], oB[16];
    #pragma unroll
    for (int t = 0; t < 16; t++) { oA[t] = 0ull; oB[t] = 0ull; }
    #pragma unroll
    for (int rr = 0; rr < 8; rr++) {
        #pragma unroll
        for (int kj = 0; kj < 7; kj++) {
            const uint32_t a = vbase + (uint32_t)((srow[rr] * WW + kj) * CS * 4);
            const int tap = rr * 7 + kj;

            uint64_t wA2 = 0ull, wB2 = 0ull;
            if (rr < 7) {
                float2 f2 = __half22float2(pAh[tap >> 1]);
                const float w = (tap & 1) ? f2.y : f2.x;
                wA2 = pack2(w, w);
            }
            {
                float2 f2 = __half22float2(pBh[tap >> 1]);
                const float w = (tap & 1) ? f2.y : f2.x;   // masked entries are exactly 0
                wB2 = pack2(w, w);
            }

            #pragma unroll
            for (int h = 0; h < 2; h++) {     // d-halved: 16-reg vt window
                uint64_t vt[8];
                #pragma unroll
                for (int u = 0; u < 4; u++) lds16(a + 64 * h + 16 * u, vt[2 * u], vt[2 * u + 1]);
                #pragma unroll
                for (int t = 0; t < 8; t++) {
                    if (rr < 7) oA[8 * h + t] = ffma2(wA2, vt[t], oA[8 * h + t]);
                    oB[8 * h + t] = ffma2(wB2, vt[t], oB[8 * h + t]);
                }
            }
        }
    }

    // ---- write out (B,256,56,56) ----
    float* oga = out + (size_t)b * (256 * PLANE) + (size_t)(head * 32) * PLANE + iA * WW + j;
    float* ogb = oga + WW;
    #pragma unroll
    for (int t = 0; t < 16; t++) {
        float2 fa = unpack2(oA[t]);
        float2 fb = unpack2(oB[t]);
        oga[(2 * t) * PLANE]     = fa.x * invA;
        oga[(2 * t + 1) * PLANE] = fa.y * invA;
        ogb[(2 * t) * PLANE]     = fb.x * invB;
        ogb[(2 * t + 1) * PLANE] = fb.y * invB;
    }
}

extern "C" void kernel_launch(void* const* d_in, const int* in_sizes, int n_in,
                              void* d_out, int out_size)
{
    const float* x   = (const float*)d_in[0];
    const float* rpb = (const float*)d_in[1];
    float* out = (float*)d_out;

    const int smem_bytes = (2 * TELEMS + 192) * sizeof(float);  // 226,560 B
    cudaFuncSetAttribute(natten7x7_kernel,
                         cudaFuncAttributeMaxDynamicSharedMemorySize, smem_bytes);

    dim3 grid(HH / ROWS, 2 * 8);   // 7 x 16 = 112 CTAs -> single wave
    dim3 block(WW, 4);             // 224 threads, each owns 2 query rows
    natten7x7_kernel<<<grid, block, smem_bytes>>>(x, rpb, out);
}